// round 15
// baseline (speedup 1.0000x reference)
#include <cuda_runtime.h>
#include <cstdint>

// single_head_local_attention: b=2, c=256, h=w=64, kernel=7, pad=3 (shapes fixed).
// out[b,c,y,x] = sum_kk softmax_kk( (1/16) * sum_c q[c,p] * k[c, p+off(kk)] ) * v[c, p+off(kk)]
// Zero padding: OOB logits are 0 and participate in softmax (matches reference).
//
// 8x4 pixel tile / block, 256 threads = 8 channel-groups (1 warp, 32 ch each).
// Warp-autonomous cp.async staging (double-buffered, commit/wait_group 1),
// OOB -> hardware zero-fill. Both main loops FULLY UNROLLED so all buffer
// offsets / channel strides / LDS addresses constant-fold into immediates.

namespace {
constexpr int Cn = 256, Hn = 64, Wn = 64, HWn = Hn * Wn;
constexpr int KS = 7, KK = 49, Rr = 3;
constexpr int TW = 8, TH = 4, NPIX = TW * TH;      // 32 pixels / block
constexpr int NG = 8, CPG = Cn / NG;               // 8 groups x 32 channels
constexpr int CHI = 2, NITER = CPG / CHI;          // 16 iterations / phase
constexpr int CHIHW = CHI * HWn;                   // channel stride per iter
constexpr int HROWS = TH + KS - 1;                 // 10
constexpr int HCOLS = TW + KS - 1;                 // 14
constexpr int HSTR = 24;                           // float4-aligned, conflict-free
constexpr int NSLOT = NG * CHI;                    // 16 halo tiles / buffer
constexpr int TILEW = HROWS * HSTR;                // 240 words / tile
constexpr int BUFW  = NSLOT * TILEW;               // 3840 words / buffer
constexpr int TELEM = HROWS * HCOLS;               // 140 elements / tile
constexpr int LOADW = CHI * TELEM;                 // 280 elements / warp / iter
constexpr int NSLW  = (LOADW + 31) / 32;           // 9 loader slots / lane
constexpr int TAILW = LOADW - (NSLW - 1) * 32;     // 24 live lanes in last slot
}

__device__ __forceinline__ void cp_async4(uint32_t dst, const void* src, int src_sz) {
    asm volatile("cp.async.ca.shared.global [%0], [%1], 4, %2;\n"
                 :: "r"(dst), "l"(src), "r"(src_sz) : "memory");
}
__device__ __forceinline__ void cp_commit() {
    asm volatile("cp.async.commit_group;\n" ::: "memory");
}
__device__ __forceinline__ void cp_wait1() {
    asm volatile("cp.async.wait_group 1;\n" ::: "memory");
}

__global__ __launch_bounds__(256, 2)
void lattn9(const float* __restrict__ qg, const float* __restrict__ kg,
            const float* __restrict__ vg, float* __restrict__ outg)
{
    __shared__ __align__(16) float halo[2 * BUFW];        // 30.7 KB double buffer
    __shared__ __align__(16) float cs[NPIX][KK];          // 6.3 KB

    const int tid  = threadIdx.x;
    const int g    = tid >> 5;          // channel group (one warp)
    const int lane = tid & 31;
    const int qid  = lane & 7;          // pixel quad id
    const int qr   = lane >> 3;         // dy-row quarter 0..3
    const int pr   = qid >> 1;          // pixel row 0..3
    const int pc4  = (qid & 1) << 2;    // pixel col 0 or 4
    const int l0   = pr * TW + pc4;     // first pixel linear id
    const int dy0  = qr << 1;           // first dy row of this quarter
    const bool r1ok = (qr < 3);         // second row valid (dy0+1 <= 6)?

    const int tx0 = blockIdx.x * TW, ty0 = blockIdx.y * TH;
    const size_t bofs = (size_t)blockIdx.z * Cn * HWn;
    const float* qb = qg + bofs;
    const float* kb = kg + bofs;
    const float* vb = vg + bofs;
    float*       ob = outg + bofs;

    // cs zero-init (consumed after the pre-reduction block barrier)
    for (int i = tid; i < NPIX * KK; i += 256) ((float*)cs)[i] = 0.f;

    // ---- per-warp loader geometry: lane stages its own warp's 2 tiles ----
    uint32_t sdst[NSLW];                // shared byte address in buffer 0
    int      soff[NSLW];                // global element offset (channel it=0)
    unsigned vm = 0;                    // in-bounds bitmask per slot
    const uint32_t hsm = (uint32_t)__cvta_generic_to_shared(halo);
    #pragma unroll
    for (int s = 0; s < NSLW; s++) {
        int idx = lane + s * 32;
        if (idx >= LOADW) idx = 0;                    // tail lanes skip at use
        int j   = (idx >= TELEM) ? 1 : 0;
        int e   = idx - j * TELEM;
        int row = e / HCOLS;
        int col = e - row * HCOLS;
        sdst[s] = hsm + 4u * (uint32_t)((2 * g + j) * TILEW + row * HSTR + col);
        int gy = ty0 - Rr + row, gx = tx0 - Rr + col;
        bool ok = ((unsigned)gy < (unsigned)Hn) && ((unsigned)gx < (unsigned)Wn);
        if (ok) vm |= (1u << s);
        soff[s] = (g * CPG + j) * HWn + (ok ? gy * Wn + gx : 0);
    }
    const bool tail = (lane < TAILW);

    // stage: constant stoff/bo fold into immediates under full unroll
    auto stage = [&](const float* base, int stoff, uint32_t bo) {
        #pragma unroll
        for (int s = 0; s < NSLW; s++) {
            if (s < NSLW - 1 || tail) {
                int sz = ((vm >> s) & 1u) ? 4 : 0;    // OOB -> zero-fill
                cp_async4(sdst[s] + bo, base + soff[s] + stoff, sz);
            }
        }
        cp_commit();
    };

    float acc[2][28];
    #pragma unroll
    for (int r = 0; r < 2; r++)
        #pragma unroll
        for (int i = 0; i < 28; i++) acc[r][i] = 0.f;

    const int hbase = (pr + dy0) * HSTR + pc4;        // quarter's first halo row

    // =================== PHASE 1: correlation (warp-autonomous) ===============
    stage(kb, 0, 0);                                  // G(0) -> buf0
    stage(kb, CHIHW, 4u * BUFW);                      // G(1) -> buf1

    const float* qp0 = qb + (size_t)(g * CPG) * HWn + (ty0 + pr) * Wn + tx0 + pc4;
    const float* hb0 = &halo[g * CHI * TILEW + hbase];

    #pragma unroll
    for (int it = 0; it < NITER; it++) {
        // q loads issued BEFORE the wait: LDG latency overlaps cp.async drain
        float4 qv0 = *(const float4*)(qp0 + it * CHIHW);
        float4 qv1 = *(const float4*)(qp0 + it * CHIHW + HWn);
        cp_wait1();                                   // G(it) complete
        __syncwarp();                                 // visible warp-wide
        const float* hb = hb0 + (it & 1) * BUFW;      // constant under unroll
        #pragma unroll
        for (int j = 0; j < CHI; j++) {
            float qa[4];
            if (j == 0) { qa[0] = qv0.x; qa[1] = qv0.y; qa[2] = qv0.z; qa[3] = qv0.w; }
            else        { qa[0] = qv1.x; qa[1] = qv1.y; qa[2] = qv1.z; qa[3] = qv1.w; }
            const float* hrow = hb + j * TILEW;
            #pragma unroll
            for (int r = 0; r < 2; r++) {
                if (r == 0 || r1ok) {
                    float4 A = *(const float4*)(hrow + r * HSTR);
                    float4 B = *(const float4*)(hrow + r * HSTR + 4);
                    float4 C = *(const float4*)(hrow + r * HSTR + 8);
                    float f[12] = {A.x, A.y, A.z, A.w, B.x, B.y, B.z, B.w,
                                   C.x, C.y, C.z, C.w};
                    #pragma unroll
                    for (int dx = 0; dx < 7; dx++)
                        #pragma unroll
                        for (int px = 0; px < 4; px++)
                            acc[r][dx * 4 + px] =
                                fmaf(qa[px], f[dx + px], acc[r][dx * 4 + px]);
                }
            }
        }
        __syncwarp();                                 // warp reads done
        if (it + 2 < NITER)
            stage(kb, (it + 2) * CHIHW, (uint32_t)((it & 1) * 4 * BUFW));
        else
            cp_commit();                              // keep group-count invariant
    }

    // phase-2 prologue staging overlaps the reduction + softmax below
    stage(vb, 0, 0);                                  // G2(0) -> buf0
    stage(vb, CHIHW, 4u * BUFW);                      // G2(1) -> buf1

    // ---- cross-warp reduction into cs[pixel][49] via shared atomics ----
    __syncthreads();                                  // cs zero-init visible
    #pragma unroll
    for (int r = 0; r < 2; r++) {
        if (r == 0 || r1ok) {
            #pragma unroll
            for (int dx = 0; dx < 7; dx++)
                #pragma unroll
                for (int px = 0; px < 4; px++)
                    atomicAdd(&cs[l0 + px][(dy0 + r) * 7 + dx], acc[r][dx * 4 + px]);
        }
    }
    __syncthreads();

    // ---- softmax over 49 offsets (one thread per pixel; logits = corr/16) ----
    if (tid < NPIX) {
        float m = -1e30f;
        #pragma unroll
        for (int kk = 0; kk < KK; kk++) m = fmaxf(m, cs[tid][kk]);
        m *= 0.0625f;
        float ssum = 0.f;
        #pragma unroll
        for (int kk = 0; kk < KK; kk++) {
            float e = __expf(fmaf(cs[tid][kk], 0.0625f, -m));
            cs[tid][kk] = e;
            ssum += e;
        }
        float inv = 1.f / ssum;
        #pragma unroll
        for (int kk = 0; kk < KK; kk++) cs[tid][kk] *= inv;
    }
    __syncthreads();

    // ---- load attention weights into registers (reuse acc) ----
    #pragma unroll
    for (int r = 0; r < 2; r++) {
        bool use = (r == 0) || r1ok;
        #pragma unroll
        for (int dx = 0; dx < 7; dx++)
            #pragma unroll
            for (int px = 0; px < 4; px++)
                acc[r][dx * 4 + px] = use ? cs[l0 + px][(dy0 + r) * 7 + dx] : 0.f;
    }
    // halo is warp-private from here on -- no block barrier needed.

    // =================== PHASE 2: attn . V (warp-autonomous) ==================
    float* op0 = ob + (size_t)(g * CPG) * HWn + (ty0 + pr) * Wn + tx0 + pc4;

    #pragma unroll
    for (int it = 0; it < NITER; it++) {
        cp_wait1();                                   // G2(it) complete
        __syncwarp();
        const float* hb = hb0 + (it & 1) * BUFW;
        #pragma unroll
        for (int j = 0; j < CHI; j++) {
            const float* hrow = hb + j * TILEW;
            float o[4] = {0.f, 0.f, 0.f, 0.f};
            #pragma unroll
            for (int r = 0; r < 2; r++) {
                if (r == 0 || r1ok) {
                    float4 A = *(const float4*)(hrow + r * HSTR);
                    float4 B = *(const float4*)(hrow + r * HSTR + 4);
                    float4 C = *(const float4*)(hrow + r * HSTR + 8);
                    float f[12] = {A.x, A.y, A.z, A.w, B.x, B.y, B.z, B.w,
                                   C.x, C.y, C.z, C.w};
                    #pragma unroll
                    for (int dx = 0; dx < 7; dx++)
                        #pragma unroll
                        for (int px = 0; px < 4; px++)
                            o[px] = fmaf(acc[r][dx * 4 + px], f[dx + px], o[px]);
                }
            }
            #pragma unroll
            for (int px = 0; px < 4; px++) {
                o[px] += __shfl_xor_sync(0xFFFFFFFFu, o[px], 8);
                o[px] += __shfl_xor_sync(0xFFFFFFFFu, o[px], 16);
            }
            if (qr == 0) {
                float4 ov; ov.x = o[0]; ov.y = o[1]; ov.z = o[2]; ov.w = o[3];
                *(float4*)(op0 + it * CHIHW + j * HWn) = ov;
            }
        }
        __syncwarp();
        if (it + 2 < NITER)
            stage(vb, (it + 2) * CHIHW, (uint32_t)((it & 1) * 4 * BUFW));
        else
            cp_commit();
    }
}

extern "C" void kernel_launch(void* const* d_in, const int* in_sizes, int n_in,
                              void* d_out, int out_size)
{
    const float* q = (const float*)d_in[0];
    const float* k = (const float*)d_in[1];
    const float* v = (const float*)d_in[2];
    float* out = (float*)d_out;

    dim3 grid(Wn / TW, Hn / TH, 2);   // (8, 16, 2) = 256 blocks
    lattn9<<<grid, 256>>>(q, k, v, out);
}

// round 16
// speedup vs baseline: 1.3598x; 1.3598x over previous
#include <cuda_runtime.h>
#include <cstdint>

// single_head_local_attention: b=2, c=256, h=w=64, kernel=7, pad=3 (shapes fixed).
// out[b,c,y,x] = sum_kk softmax_kk( (1/16) * sum_c q[c,p] * k[c, p+off(kk)] ) * v[c, p+off(kk)]
// Zero padding: OOB logits are 0 and participate in softmax (matches reference).
//
// 8x4 pixel tile / block, 256 threads = 8 channel-groups (1 warp, 32 ch each).
// Warp-autonomous cp.async staging (double-buffered, commit/wait_group 1),
// OOB -> hardware zero-fill. Main loops unrolled BY 2 (not fully): (it&1)
// constant-folds per copy while SASS stays inside the I$ plateau.

namespace {
constexpr int Cn = 256, Hn = 64, Wn = 64, HWn = Hn * Wn;
constexpr int KS = 7, KK = 49, Rr = 3;
constexpr int TW = 8, TH = 4, NPIX = TW * TH;      // 32 pixels / block
constexpr int NG = 8, CPG = Cn / NG;               // 8 groups x 32 channels
constexpr int CHI = 2, NITER = CPG / CHI;          // 16 iterations / phase
constexpr int CHIHW = CHI * HWn;                   // channel stride per iter
constexpr int HROWS = TH + KS - 1;                 // 10
constexpr int HCOLS = TW + KS - 1;                 // 14
constexpr int HSTR = 24;                           // float4-aligned, conflict-free
constexpr int NSLOT = NG * CHI;                    // 16 halo tiles / buffer
constexpr int TILEW = HROWS * HSTR;                // 240 words / tile
constexpr int BUFW  = NSLOT * TILEW;               // 3840 words / buffer
constexpr int TELEM = HROWS * HCOLS;               // 140 elements / tile
constexpr int LOADW = CHI * TELEM;                 // 280 elements / warp / iter
constexpr int NSLW  = (LOADW + 31) / 32;           // 9 loader slots / lane
constexpr int TAILW = LOADW - (NSLW - 1) * 32;     // 24 live lanes in last slot
}

__device__ __forceinline__ void cp_async4(uint32_t dst, const void* src, int src_sz) {
    asm volatile("cp.async.ca.shared.global [%0], [%1], 4, %2;\n"
                 :: "r"(dst), "l"(src), "r"(src_sz) : "memory");
}
__device__ __forceinline__ void cp_commit() {
    asm volatile("cp.async.commit_group;\n" ::: "memory");
}
__device__ __forceinline__ void cp_wait1() {
    asm volatile("cp.async.wait_group 1;\n" ::: "memory");
}

__global__ __launch_bounds__(256, 2)
void lattn10(const float* __restrict__ qg, const float* __restrict__ kg,
             const float* __restrict__ vg, float* __restrict__ outg)
{
    __shared__ __align__(16) float halo[2 * BUFW];        // 30.7 KB double buffer
    __shared__ __align__(16) float cs[NPIX][KK];          // 6.3 KB

    const int tid  = threadIdx.x;
    const int g    = tid >> 5;          // channel group (one warp)
    const int lane = tid & 31;
    const int qid  = lane & 7;          // pixel quad id
    const int qr   = lane >> 3;         // dy-row quarter 0..3
    const int pr   = qid >> 1;          // pixel row 0..3
    const int pc4  = (qid & 1) << 2;    // pixel col 0 or 4
    const int l0   = pr * TW + pc4;     // first pixel linear id
    const int dy0  = qr << 1;           // first dy row of this quarter
    const bool r1ok = (qr < 3);         // second row valid (dy0+1 <= 6)?

    const int tx0 = blockIdx.x * TW, ty0 = blockIdx.y * TH;
    const size_t bofs = (size_t)blockIdx.z * Cn * HWn;
    const float* qb = qg + bofs;
    const float* kb = kg + bofs;
    const float* vb = vg + bofs;
    float*       ob = outg + bofs;

    // cs zero-init (consumed after the pre-reduction block barrier)
    for (int i = tid; i < NPIX * KK; i += 256) ((float*)cs)[i] = 0.f;

    // ---- per-warp loader geometry: lane stages its own warp's 2 tiles ----
    uint32_t sdst[NSLW];                // shared byte address in buffer 0
    int      soff[NSLW];                // global element offset (channel it=0)
    unsigned vm = 0;                    // in-bounds bitmask per slot
    const uint32_t hsm = (uint32_t)__cvta_generic_to_shared(halo);
    #pragma unroll
    for (int s = 0; s < NSLW; s++) {
        int idx = lane + s * 32;
        if (idx >= LOADW) idx = 0;                    // tail lanes skip at use
        int j   = (idx >= TELEM) ? 1 : 0;
        int e   = idx - j * TELEM;
        int row = e / HCOLS;
        int col = e - row * HCOLS;
        sdst[s] = hsm + 4u * (uint32_t)((2 * g + j) * TILEW + row * HSTR + col);
        int gy = ty0 - Rr + row, gx = tx0 - Rr + col;
        bool ok = ((unsigned)gy < (unsigned)Hn) && ((unsigned)gx < (unsigned)Wn);
        if (ok) vm |= (1u << s);
        soff[s] = (g * CPG + j) * HWn + (ok ? gy * Wn + gx : 0);
    }
    const bool tail = (lane < TAILW);

    // stage iteration 'stoff = it*CHIHW' into buffer byte-offset bo
    auto stage = [&](const float* base, int stoff, uint32_t bo) {
        #pragma unroll
        for (int s = 0; s < NSLW; s++) {
            if (s < NSLW - 1 || tail) {
                int sz = ((vm >> s) & 1u) ? 4 : 0;    // OOB -> zero-fill
                cp_async4(sdst[s] + bo, base + soff[s] + stoff, sz);
            }
        }
        cp_commit();
    };

    float acc[2][28];
    #pragma unroll
    for (int r = 0; r < 2; r++)
        #pragma unroll
        for (int i = 0; i < 28; i++) acc[r][i] = 0.f;

    const int hbase = (pr + dy0) * HSTR + pc4;        // quarter's first halo row

    // =================== PHASE 1: correlation (warp-autonomous) ===============
    stage(kb, 0, 0);                                  // G(0) -> buf0
    stage(kb, CHIHW, 4u * BUFW);                      // G(1) -> buf1

    const float* qp = qb + (size_t)(g * CPG) * HWn + (ty0 + pr) * Wn + tx0 + pc4;

    #pragma unroll 2
    for (int it = 0; it < NITER; it++) {
        // q loads issued BEFORE the wait: LDG latency overlaps cp.async drain
        float4 qv0 = *(const float4*)qp;
        float4 qv1 = *(const float4*)(qp + HWn);
        qp += CHIHW;
        cp_wait1();                                   // G(it) complete
        __syncwarp();                                 // visible warp-wide
        const float* hb = &halo[(it & 1) * BUFW + g * CHI * TILEW + hbase];
        #pragma unroll
        for (int j = 0; j < CHI; j++) {
            float qa[4];
            if (j == 0) { qa[0] = qv0.x; qa[1] = qv0.y; qa[2] = qv0.z; qa[3] = qv0.w; }
            else        { qa[0] = qv1.x; qa[1] = qv1.y; qa[2] = qv1.z; qa[3] = qv1.w; }
            const float* hrow = hb + j * TILEW;
            #pragma unroll
            for (int r = 0; r < 2; r++) {
                if (r == 0 || r1ok) {
                    float4 A = *(const float4*)(hrow + r * HSTR);
                    float4 B = *(const float4*)(hrow + r * HSTR + 4);
                    float4 C = *(const float4*)(hrow + r * HSTR + 8);
                    float f[12] = {A.x, A.y, A.z, A.w, B.x, B.y, B.z, B.w,
                                   C.x, C.y, C.z, C.w};
                    #pragma unroll
                    for (int dx = 0; dx < 7; dx++)
                        #pragma unroll
                        for (int px = 0; px < 4; px++)
                            acc[r][dx * 4 + px] =
                                fmaf(qa[px], f[dx + px], acc[r][dx * 4 + px]);
                }
            }
        }
        __syncwarp();                                 // warp reads done
        if (it + 2 < NITER)
            stage(kb, (it + 2) * CHIHW, (uint32_t)((it & 1) * 4 * BUFW));
        else
            cp_commit();                              // keep group-count invariant
    }

    // phase-2 prologue staging overlaps the reduction + softmax below
    stage(vb, 0, 0);                                  // G2(0) -> buf0
    stage(vb, CHIHW, 4u * BUFW);                      // G2(1) -> buf1

    // ---- cross-warp reduction into cs[pixel][49] via shared atomics ----
    __syncthreads();                                  // cs zero-init visible
    #pragma unroll
    for (int r = 0; r < 2; r++) {
        if (r == 0 || r1ok) {
            #pragma unroll
            for (int dx = 0; dx < 7; dx++)
                #pragma unroll
                for (int px = 0; px < 4; px++)
                    atomicAdd(&cs[l0 + px][(dy0 + r) * 7 + dx], acc[r][dx * 4 + px]);
        }
    }
    __syncthreads();

    // ---- softmax over 49 offsets (one thread per pixel; logits = corr/16) ----
    if (tid < NPIX) {
        float m = -1e30f;
        #pragma unroll
        for (int kk = 0; kk < KK; kk++) m = fmaxf(m, cs[tid][kk]);
        m *= 0.0625f;
        float ssum = 0.f;
        #pragma unroll
        for (int kk = 0; kk < KK; kk++) {
            float e = __expf(fmaf(cs[tid][kk], 0.0625f, -m));
            cs[tid][kk] = e;
            ssum += e;
        }
        float inv = 1.f / ssum;
        #pragma unroll
        for (int kk = 0; kk < KK; kk++) cs[tid][kk] *= inv;
    }
    __syncthreads();

    // ---- load attention weights into registers (reuse acc) ----
    #pragma unroll
    for (int r = 0; r < 2; r++) {
        bool use = (r == 0) || r1ok;
        #pragma unroll
        for (int dx = 0; dx < 7; dx++)
            #pragma unroll
            for (int px = 0; px < 4; px++)
                acc[r][dx * 4 + px] = use ? cs[l0 + px][(dy0 + r) * 7 + dx] : 0.f;
    }
    // halo is warp-private from here on -- no block barrier needed.

    // =================== PHASE 2: attn . V (warp-autonomous) ==================
    float* op = ob + (size_t)(g * CPG) * HWn + (ty0 + pr) * Wn + tx0 + pc4;

    #pragma unroll 2
    for (int it = 0; it < NITER; it++) {
        cp_wait1();                                   // G2(it) complete
        __syncwarp();
        const float* hb = &halo[(it & 1) * BUFW + g * CHI * TILEW + hbase];
        #pragma unroll
        for (int j = 0; j < CHI; j++) {
            const float* hrow = hb + j * TILEW;
            float o[4] = {0.f, 0.f, 0.f, 0.f};
            #pragma unroll
            for (int r = 0; r < 2; r++) {
                if (r == 0 || r1ok) {
                    float4 A = *(const float4*)(hrow + r * HSTR);
                    float4 B = *(const float4*)(hrow + r * HSTR + 4);
                    float4 C = *(const float4*)(hrow + r * HSTR + 8);
                    float f[12] = {A.x, A.y, A.z, A.w, B.x, B.y, B.z, B.w,
                                   C.x, C.y, C.z, C.w};
                    #pragma unroll
                    for (int dx = 0; dx < 7; dx++)
                        #pragma unroll
                        for (int px = 0; px < 4; px++)
                            o[px] = fmaf(acc[r][dx * 4 + px], f[dx + px], o[px]);
                }
            }
            #pragma unroll
            for (int px = 0; px < 4; px++) {
                o[px] += __shfl_xor_sync(0xFFFFFFFFu, o[px], 8);
                o[px] += __shfl_xor_sync(0xFFFFFFFFu, o[px], 16);
            }
            if (qr == 0) {
                float4 ov; ov.x = o[0]; ov.y = o[1]; ov.z = o[2]; ov.w = o[3];
                *(float4*)op = ov;
            }
            op += HWn;
        }
        __syncwarp();
        if (it + 2 < NITER)
            stage(vb, (it + 2) * CHIHW, (uint32_t)((it & 1) * 4 * BUFW));
        else
            cp_commit();
    }
}

extern "C" void kernel_launch(void* const* d_in, const int* in_sizes, int n_in,
                              void* d_out, int out_size)
{
    const float* q = (const float*)d_in[0];
    const float* k = (const float*)d_in[1];
    const float* v = (const float*)d_in[2];
    float* out = (float*)d_out;

    dim3 grid(Wn / TW, Hn / TH, 2);   // (8, 16, 2) = 256 blocks
    lattn10<<<grid, 256>>>(q, k, v, out);
}

// round 17
// speedup vs baseline: 1.4191x; 1.0436x over previous
#include <cuda_runtime.h>
#include <cstdint>

// single_head_local_attention: b=2, c=256, h=w=64, kernel=7, pad=3 (shapes fixed).
// out[b,c,y,x] = sum_kk softmax_kk( (1/16) * sum_c q[c,p] * k[c, p+off(kk)] ) * v[c, p+off(kk)]
// Zero padding: OOB logits are 0 and participate in softmax (matches reference).
//
// 8x4 pixel tile / block, 256 threads = 8 channel-groups (1 warp, 32 ch each).
// TRIPLE-buffered warp-autonomous cp.async staging (commit/wait_group 2):
// prefetch distance 3 iterations. cs[32][49] is aliased over buffer 2 (only
// live between the phases, when buffer 2 is idle). OOB -> hw zero-fill.

namespace {
constexpr int Cn = 256, Hn = 64, Wn = 64, HWn = Hn * Wn;
constexpr int KS = 7, KK = 49, Rr = 3;
constexpr int TW = 8, TH = 4, NPIX = TW * TH;      // 32 pixels / block
constexpr int NG = 8, CPG = Cn / NG;               // 8 groups x 32 channels
constexpr int CHI = 2, NITER = CPG / CHI;          // 16 iterations / phase
constexpr int CHIHW = CHI * HWn;                   // channel stride per iter
constexpr int HROWS = TH + KS - 1;                 // 10
constexpr int HCOLS = TW + KS - 1;                 // 14
constexpr int HSTR = 24;                           // float4-aligned, conflict-free
constexpr int NSLOT = NG * CHI;                    // 16 halo tiles / buffer
constexpr int TILEW = HROWS * HSTR;                // 240 words / tile
constexpr int BUFW  = NSLOT * TILEW;               // 3840 words / buffer
constexpr int TELEM = HROWS * HCOLS;               // 140 elements / tile
constexpr int LOADW = CHI * TELEM;                 // 280 elements / warp / iter
constexpr int NSLW  = (LOADW + 31) / 32;           // 9 loader slots / lane
constexpr int TAILW = LOADW - (NSLW - 1) * 32;     // 24 live lanes in last slot
}

__device__ __forceinline__ void cp_async4(uint32_t dst, const void* src, int src_sz) {
    asm volatile("cp.async.ca.shared.global [%0], [%1], 4, %2;\n"
                 :: "r"(dst), "l"(src), "r"(src_sz) : "memory");
}
__device__ __forceinline__ void cp_commit() {
    asm volatile("cp.async.commit_group;\n" ::: "memory");
}
__device__ __forceinline__ void cp_wait2() {
    asm volatile("cp.async.wait_group 2;\n" ::: "memory");
}

__global__ __launch_bounds__(256, 2)
void lattn11(const float* __restrict__ qg, const float* __restrict__ kg,
             const float* __restrict__ vg, float* __restrict__ outg)
{
    __shared__ __align__(16) float halo[3 * BUFW];        // 46.1 KB triple buffer
    // cs aliased over buffer 2 (live only between the phases)
    float (*cs)[KK] = reinterpret_cast<float(*)[KK]>(halo + 2 * BUFW);

    const int tid  = threadIdx.x;
    const int g    = tid >> 5;          // channel group (one warp)
    const int lane = tid & 31;
    const int qid  = lane & 7;          // pixel quad id
    const int qr   = lane >> 3;         // dy-row quarter 0..3
    const int pr   = qid >> 1;          // pixel row 0..3
    const int pc4  = (qid & 1) << 2;    // pixel col 0 or 4
    const int l0   = pr * TW + pc4;     // first pixel linear id
    const int dy0  = qr << 1;           // first dy row of this quarter
    const bool r1ok = (qr < 3);         // second row valid (dy0+1 <= 6)?

    const int tx0 = blockIdx.x * TW, ty0 = blockIdx.y * TH;
    const size_t bofs = (size_t)blockIdx.z * Cn * HWn;
    const float* qb = qg + bofs;
    const float* kb = kg + bofs;
    const float* vb = vg + bofs;
    float*       ob = outg + bofs;

    // ---- per-warp loader geometry: lane stages its own warp's 2 tiles ----
    uint32_t sdst[NSLW];                // shared byte address in buffer 0
    int      soff[NSLW];                // global element offset (channel it=0)
    unsigned vm = 0;                    // in-bounds bitmask per slot
    const uint32_t hsm = (uint32_t)__cvta_generic_to_shared(halo);
    #pragma unroll
    for (int s = 0; s < NSLW; s++) {
        int idx = lane + s * 32;
        if (idx >= LOADW) idx = 0;                    // tail lanes skip at use
        int j   = (idx >= TELEM) ? 1 : 0;
        int e   = idx - j * TELEM;
        int row = e / HCOLS;
        int col = e - row * HCOLS;
        sdst[s] = hsm + 4u * (uint32_t)((2 * g + j) * TILEW + row * HSTR + col);
        int gy = ty0 - Rr + row, gx = tx0 - Rr + col;
        bool ok = ((unsigned)gy < (unsigned)Hn) && ((unsigned)gx < (unsigned)Wn);
        if (ok) vm |= (1u << s);
        soff[s] = (g * CPG + j) * HWn + (ok ? gy * Wn + gx : 0);
    }
    const bool tail = (lane < TAILW);

    // stage iteration 'stoff = it*CHIHW' into buffer byte-offset bo
    auto stage = [&](const float* base, int stoff, uint32_t bo) {
        #pragma unroll
        for (int s = 0; s < NSLW; s++) {
            if (s < NSLW - 1 || tail) {
                int sz = ((vm >> s) & 1u) ? 4 : 0;    // OOB -> zero-fill
                cp_async4(sdst[s] + bo, base + soff[s] + stoff, sz);
            }
        }
        cp_commit();
    };

    float acc[2][28];
    #pragma unroll
    for (int r = 0; r < 2; r++)
        #pragma unroll
        for (int i = 0; i < 28; i++) acc[r][i] = 0.f;

    const int hbase = (pr + dy0) * HSTR + pc4;        // quarter's first halo row

    // =================== PHASE 1: correlation (warp-autonomous) ===============
    stage(kb, 0, 0);                                  // G(0) -> buf0
    stage(kb, CHIHW, 4u * BUFW);                      // G(1) -> buf1
    stage(kb, 2 * CHIHW, 8u * BUFW);                  // G(2) -> buf2

    const float* qp = qb + (size_t)(g * CPG) * HWn + (ty0 + pr) * Wn + tx0 + pc4;

    int rb = 0;                                       // read-buffer index (it%3)
    for (int it = 0; it < NITER; it++) {
        // q loads issued BEFORE the wait: LDG latency overlaps cp.async drain
        float4 qv0 = *(const float4*)qp;
        float4 qv1 = *(const float4*)(qp + HWn);
        qp += CHIHW;
        cp_wait2();                                   // G(it) complete
        __syncwarp();                                 // visible warp-wide
        const float* hb = &halo[rb * BUFW + g * CHI * TILEW + hbase];
        #pragma unroll
        for (int j = 0; j < CHI; j++) {
            float qa[4];
            if (j == 0) { qa[0] = qv0.x; qa[1] = qv0.y; qa[2] = qv0.z; qa[3] = qv0.w; }
            else        { qa[0] = qv1.x; qa[1] = qv1.y; qa[2] = qv1.z; qa[3] = qv1.w; }
            const float* hrow = hb + j * TILEW;
            #pragma unroll
            for (int r = 0; r < 2; r++) {
                if (r == 0 || r1ok) {
                    float4 A = *(const float4*)(hrow + r * HSTR);
                    float4 B = *(const float4*)(hrow + r * HSTR + 4);
                    float4 C = *(const float4*)(hrow + r * HSTR + 8);
                    float f[12] = {A.x, A.y, A.z, A.w, B.x, B.y, B.z, B.w,
                                   C.x, C.y, C.z, C.w};
                    #pragma unroll
                    for (int dx = 0; dx < 7; dx++)
                        #pragma unroll
                        for (int px = 0; px < 4; px++)
                            acc[r][dx * 4 + px] =
                                fmaf(qa[px], f[dx + px], acc[r][dx * 4 + px]);
                }
            }
        }
        __syncwarp();                                 // warp reads done
        if (it + 3 < NITER)
            stage(kb, (it + 3) * CHIHW, (uint32_t)(rb * 4 * BUFW));
        else
            cp_commit();                              // keep group-count invariant
        rb = (rb == 2) ? 0 : rb + 1;
    }

    // V staging for buf0/buf1 overlaps the reduction + softmax below
    stage(vb, 0, 0);                                  // G2(0) -> buf0
    stage(vb, CHIHW, 4u * BUFW);                      // G2(1) -> buf1

    // ---- all warps past their buf2 reads before cs (aliased) is zeroed ----
    __syncthreads();
    for (int i = tid; i < NPIX * KK; i += 256) ((float*)cs)[i] = 0.f;
    __syncthreads();

    // ---- cross-warp reduction into cs[pixel][49] via shared atomics ----
    #pragma unroll
    for (int r = 0; r < 2; r++) {
        if (r == 0 || r1ok) {
            #pragma unroll
            for (int dx = 0; dx < 7; dx++)
                #pragma unroll
                for (int px = 0; px < 4; px++)
                    atomicAdd(&cs[l0 + px][(dy0 + r) * 7 + dx], acc[r][dx * 4 + px]);
        }
    }
    __syncthreads();

    // ---- softmax over 49 offsets (one thread per pixel; logits = corr/16) ----
    if (tid < NPIX) {
        float m = -1e30f;
        #pragma unroll
        for (int kk = 0; kk < KK; kk++) m = fmaxf(m, cs[tid][kk]);
        m *= 0.0625f;
        float ssum = 0.f;
        #pragma unroll
        for (int kk = 0; kk < KK; kk++) {
            float e = __expf(fmaf(cs[tid][kk], 0.0625f, -m));
            cs[tid][kk] = e;
            ssum += e;
        }
        float inv = 1.f / ssum;
        #pragma unroll
        for (int kk = 0; kk < KK; kk++) cs[tid][kk] *= inv;
    }
    __syncthreads();

    // ---- load attention weights into registers (reuse acc) ----
    #pragma unroll
    for (int r = 0; r < 2; r++) {
        bool use = (r == 0) || r1ok;
        #pragma unroll
        for (int dx = 0; dx < 7; dx++)
            #pragma unroll
            for (int px = 0; px < 4; px++)
                acc[r][dx * 4 + px] = use ? cs[l0 + px][(dy0 + r) * 7 + dx] : 0.f;
    }
    __syncthreads();   // cs reads done everywhere before buf2 (alias) is restaged
    stage(vb, 2 * CHIHW, 8u * BUFW);                  // G2(2) -> buf2

    // =================== PHASE 2: attn . V (warp-autonomous) ==================
    float* op = ob + (size_t)(g * CPG) * HWn + (ty0 + pr) * Wn + tx0 + pc4;

    rb = 0;
    for (int it = 0; it < NITER; it++) {
        cp_wait2();                                   // G2(it) complete
        __syncwarp();
        const float* hb = &halo[rb * BUFW + g * CHI * TILEW + hbase];
        #pragma unroll
        for (int j = 0; j < CHI; j++) {
            const float* hrow = hb + j * TILEW;
            float o[4] = {0.f, 0.f, 0.f, 0.f};
            #pragma unroll
            for (int r = 0; r < 2; r++) {
                if (r == 0 || r1ok) {
                    float4 A = *(const float4*)(hrow + r * HSTR);
                    float4 B = *(const float4*)(hrow + r * HSTR + 4);
                    float4 C = *(const float4*)(hrow + r * HSTR + 8);
                    float f[12] = {A.x, A.y, A.z, A.w, B.x, B.y, B.z, B.w,
                                   C.x, C.y, C.z, C.w};
                    #pragma unroll
                    for (int dx = 0; dx < 7; dx++)
                        #pragma unroll
                        for (int px = 0; px < 4; px++)
                            o[px] = fmaf(acc[r][dx * 4 + px], f[dx + px], o[px]);
                }
            }
            #pragma unroll
            for (int px = 0; px < 4; px++) {
                o[px] += __shfl_xor_sync(0xFFFFFFFFu, o[px], 8);
                o[px] += __shfl_xor_sync(0xFFFFFFFFu, o[px], 16);
            }
            if (qr == 0) {
                float4 ov; ov.x = o[0]; ov.y = o[1]; ov.z = o[2]; ov.w = o[3];
                *(float4*)op = ov;
            }
            op += HWn;
        }
        __syncwarp();
        if (it + 3 < NITER)
            stage(vb, (it + 3) * CHIHW, (uint32_t)(rb * 4 * BUFW));
        else
            cp_commit();
        rb = (rb == 2) ? 0 : rb + 1;
    }
}

extern "C" void kernel_launch(void* const* d_in, const int* in_sizes, int n_in,
                              void* d_out, int out_size)
{
    const float* q = (const float*)d_in[0];
    const float* k = (const float*)d_in[1];
    const float* v = (const float*)d_in[2];
    float* out = (float*)d_out;

    dim3 grid(Wn / TW, Hn / TH, 2);   // (8, 16, 2) = 256 blocks
    lattn11<<<grid, 256>>>(q, k, v, out);
}